// round 11
// baseline (speedup 1.0000x reference)
#include <cuda_runtime.h>
#include <math.h>

#define NU 50000
#define NI 40000
#define NN 90000
#define D  64
#define EH 500000
#define E  1000000
#define OD 192

typedef unsigned int uint;

// ------------------- scratch (static device globals; no allocation) -------------------
__device__ int   g_is64;
__device__ int   g_src[E];
__device__ int   g_dst[E];
__device__ int   g_degG[NN];
__device__ int   g_offG[NN];
__device__ int   g_curG[NN];
__device__ int   g_bsum[128];
__device__ int   g_csrG_src[E];
__device__ float g_e[E];
__device__ float g_alpha[2 * E];
__device__ float g_wc[E];
__device__ __align__(16) float g_xm[2 * NN * D];
__device__ __align__(16) float g_hx[2 * NN * D];

__device__ __forceinline__ float lrelu(float v) { return v >= 0.f ? v : 0.01f * v; }
static inline int divup(int a, int b) { return (a + b - 1) / b; }

// ------------------- mma helpers -------------------
__device__ __forceinline__ void split_tf32(float a, uint& hi, uint& lo) {
    asm("cvt.rna.tf32.f32 %0, %1;" : "=r"(hi) : "f"(a));
    float d = a - __uint_as_float(hi);
    asm("cvt.rna.tf32.f32 %0, %1;" : "=r"(lo) : "f"(d));
}
__device__ __forceinline__ void mma8(float* c, const uint* a, const uint* b) {
    asm("mma.sync.aligned.m16n8k8.row.col.f32.tf32.tf32.f32 "
        "{%0,%1,%2,%3},{%4,%5,%6,%7},{%8,%9},{%0,%1,%2,%3};"
        : "+f"(c[0]), "+f"(c[1]), "+f"(c[2]), "+f"(c[3])
        : "r"(a[0]), "r"(a[1]), "r"(a[2]), "r"(a[3]), "r"(b[0]), "r"(b[1]));
}

// ------------------- edge dtype sniff -------------------
__global__ void k_sniff(const int* __restrict__ ei32) {
    int lane = threadIdx.x;
    int nz = 0;
    for (int i = lane; i < 512; i += 32)
        if (ei32[2 * i + 1] != 0) nz++;
    #pragma unroll
    for (int o = 16; o; o >>= 1) nz += __shfl_xor_sync(0xffffffffu, nz, o);
    if (lane == 0) g_is64 = (nz == 0) ? 1 : 0;
}

// ------------------- graph construction -------------------
__global__ void k_zero() {
    int i = blockIdx.x * blockDim.x + threadIdx.x;
    if (i < NN) g_degG[i] = 0;
}

__global__ void k_build(const void* __restrict__ eiRaw) {
    int i = blockIdx.x * blockDim.x + threadIdx.x;
    if (i >= E) return;
    int s, d;
    if (g_is64) {
        const long long* e64 = (const long long*)eiRaw;
        s = (int)e64[i];
        d = (int)e64[E + i];
    } else {
        const int* e32 = (const int*)eiRaw;
        s = e32[i];
        d = e32[E + i];
    }
    if ((unsigned)s >= NN) s = 0;
    if ((unsigned)d >= NN) d = 0;
    g_src[i] = s;
    g_dst[i] = d;
    atomicAdd(&g_degG[d], 1);
}

__global__ void k_scan1() {
    __shared__ int sh[1024];
    int t = threadIdx.x;
    int i = blockIdx.x * 1024 + t;
    int v = (i < NN) ? g_degG[i] : 0;
    sh[t] = v;
    __syncthreads();
    for (int st = 1; st < 1024; st <<= 1) {
        int x = (t >= st) ? sh[t - st] : 0;
        __syncthreads();
        sh[t] += x;
        __syncthreads();
    }
    if (i < NN) g_offG[i] = sh[t] - v;
    if (t == 1023) g_bsum[blockIdx.x] = sh[1023];
}

__global__ void k_scan2(int nb) {
    __shared__ int sh[128];
    int t = threadIdx.x;
    int v = (t < nb) ? g_bsum[t] : 0;
    sh[t] = v;
    __syncthreads();
    for (int st = 1; st < 128; st <<= 1) {
        int x = (t >= st) ? sh[t - st] : 0;
        __syncthreads();
        sh[t] += x;
        __syncthreads();
    }
    if (t < nb) g_bsum[t] = sh[t] - v;
}

__global__ void k_scan3() {
    int i = blockIdx.x * 1024 + threadIdx.x;
    if (i < NN) {
        int o = g_offG[i] + g_bsum[blockIdx.x];
        g_offG[i] = o;
        g_curG[i] = o;
    }
}

__global__ void k_place() {
    int i = blockIdx.x * blockDim.x + threadIdx.x;
    if (i >= E) return;
    int p = atomicAdd(&g_curG[g_dst[i]], 1);
    if ((unsigned)p < E) g_csrG_src[p] = g_src[i];
}

// ------------------- tensor-core GEMM (3xTF32) + bias + leaky -------------------
// C = leaky(A[NI,K] @ W[K,64] + bias), block tile 128x64, K-tile 32,
// 8 warps as 4(m) x 2(n), warp tile 32x32 = 2x4 m16n8k8 mma tiles.
__global__ __launch_bounds__(256) void k_gemm_mma(
    const float* __restrict__ A, const float* __restrict__ Bm,
    const float* __restrict__ bias, int mod, int K)
{
    float* C = g_xm + (size_t)mod * NN * D + (size_t)NU * D;
    __shared__ __align__(16) float sA[128][36];   // [m][k], 36 mod 32 = 4 -> bank 4g+tid
    __shared__ __align__(16) float sB[32][72];    // [k][n], 72 mod 32 = 8 -> bank 8tid+g
    int t    = threadIdx.x;
    int lane = t & 31;
    int wid  = t >> 5;
    int mw   = (wid & 3) * 32;     // warp m-strip
    int nw   = (wid >> 2) * 32;    // warp n-strip
    int g    = lane >> 2;          // group id 0..7
    int tid4 = lane & 3;           // thread-in-group 0..3
    int m0   = blockIdx.x * 128;

    // loader indices
    int la_r = t >> 3;             // 0..31 (+p*32)
    int la_c = (t & 7) * 4;        // 0..28
    int lb_k = t >> 4;             // 0..15 (+16)
    int lb_c = (t & 15) * 4;       // 0..60

    float c[2][4][4];
    #pragma unroll
    for (int i = 0; i < 2; i++)
        #pragma unroll
        for (int j = 0; j < 4; j++)
            #pragma unroll
            for (int q = 0; q < 4; q++) c[i][j][q] = 0.f;

    for (int kt = 0; kt < K; kt += 32) {
        #pragma unroll
        for (int p = 0; p < 4; p++) {
            int m = la_r + p * 32;
            int gm = m0 + m;
            float4 av = make_float4(0.f, 0.f, 0.f, 0.f);
            if (gm < NI) av = *(const float4*)&A[(size_t)gm * K + kt + la_c];
            *(float4*)&sA[m][la_c] = av;
        }
        #pragma unroll
        for (int p = 0; p < 2; p++) {
            int k = lb_k + p * 16;
            *(float4*)&sB[k][lb_c] = *(const float4*)&Bm[(size_t)(kt + k) * 64 + lb_c];
        }
        __syncthreads();

        #pragma unroll
        for (int k8 = 0; k8 < 32; k8 += 8) {
            uint ab[2][4], as_[2][4];
            #pragma unroll
            for (int mt = 0; mt < 2; mt++) {
                int mr = mw + mt * 16;
                float a0 = sA[mr + g][k8 + tid4];
                float a1 = sA[mr + g + 8][k8 + tid4];
                float a2 = sA[mr + g][k8 + tid4 + 4];
                float a3 = sA[mr + g + 8][k8 + tid4 + 4];
                split_tf32(a0, ab[mt][0], as_[mt][0]);
                split_tf32(a1, ab[mt][1], as_[mt][1]);
                split_tf32(a2, ab[mt][2], as_[mt][2]);
                split_tf32(a3, ab[mt][3], as_[mt][3]);
            }
            uint bb[4][2], bs[4][2];
            #pragma unroll
            for (int nt = 0; nt < 4; nt++) {
                int nc = nw + nt * 8 + g;
                float b0 = sB[k8 + tid4][nc];
                float b1 = sB[k8 + tid4 + 4][nc];
                split_tf32(b0, bb[nt][0], bs[nt][0]);
                split_tf32(b1, bb[nt][1], bs[nt][1]);
            }
            #pragma unroll
            for (int mt = 0; mt < 2; mt++)
                #pragma unroll
                for (int nt = 0; nt < 4; nt++) {
                    mma8(c[mt][nt], ab[mt], bb[nt]);
                    mma8(c[mt][nt], ab[mt], bs[nt]);
                    mma8(c[mt][nt], as_[mt], bb[nt]);
                }
        }
        __syncthreads();
    }

    // epilogue: bias + leaky (l2norm is a separate kernel)
    float bcol[8];
    #pragma unroll
    for (int nt = 0; nt < 4; nt++) {
        bcol[nt * 2]     = bias[nw + nt * 8 + 2 * tid4];
        bcol[nt * 2 + 1] = bias[nw + nt * 8 + 2 * tid4 + 1];
    }
    #pragma unroll
    for (int mt = 0; mt < 2; mt++) {
        #pragma unroll
        for (int half = 0; half < 2; half++) {
            int gr = m0 + mw + mt * 16 + g + half * 8;
            if (gr < NI) {
                float* crow = C + (size_t)gr * 64 + nw;
                #pragma unroll
                for (int nt = 0; nt < 4; nt++) {
                    float v0 = lrelu(c[mt][nt][half * 2]     + bcol[nt * 2]);
                    float v1 = lrelu(c[mt][nt][half * 2 + 1] + bcol[nt * 2 + 1]);
                    float2 o2 = make_float2(v0, v1);
                    *(float2*)&crow[nt * 8 + 2 * tid4] = o2;
                }
            }
        }
    }
}

// l2norm item-feature rows of xm[mod] in place (NI rows). Warp per row.
__global__ void k_l2norm_feat(int mod) {
    int row = blockIdx.x * 8 + (threadIdx.x >> 5);
    if (row >= NI) return;
    float* f = g_xm + (size_t)mod * NN * D + (size_t)(NU + row) * D;
    int lane = threadIdx.x & 31;
    float a = f[lane];
    float b = f[32 + lane];
    float ss = a * a + b * b;
    #pragma unroll
    for (int o = 16; o; o >>= 1) ss += __shfl_xor_sync(0xffffffffu, ss, o);
    float inv = rsqrtf(fmaxf(ss, 1e-24f));
    f[lane]      = a * inv;
    f[32 + lane] = b * inv;
}

// pref rows of xm[mod] = l2norm(input) (NU rows).
__global__ void k_l2norm_pref(const float* __restrict__ in, int mod) {
    int row = blockIdx.x * 8 + (threadIdx.x >> 5);
    if (row >= NU) return;
    float* p = g_xm + (size_t)mod * NN * D + (size_t)row * D;
    int lane = threadIdx.x & 31;
    float a = in[(size_t)row * 64 + lane];
    float b = in[(size_t)row * 64 + 32 + lane];
    float ss = a * a + b * b;
    #pragma unroll
    for (int o = 16; o; o >>= 1) ss += __shfl_xor_sync(0xffffffffu, ss, o);
    float inv = rsqrtf(fmaxf(ss, 1e-24f));
    p[lane]      = a * inv;
    p[32 + lane] = b * inv;
}

// g_hx slot0 = l2norm(id_emb) (NN rows).
__global__ void k_l2norm_x(const float* __restrict__ in) {
    int row = blockIdx.x * 8 + (threadIdx.x >> 5);
    if (row >= NN) return;
    int lane = threadIdx.x & 31;
    float a = in[(size_t)row * 64 + lane];
    float b = in[(size_t)row * 64 + 32 + lane];
    float ss = a * a + b * b;
    #pragma unroll
    for (int o = 16; o; o >>= 1) ss += __shfl_xor_sync(0xffffffffu, ss, o);
    float inv = rsqrtf(fmaxf(ss, 1e-24f));
    g_hx[(size_t)row * 64 + lane]      = a * inv;
    g_hx[(size_t)row * 64 + 32 + lane] = b * inv;
}

// ------------------- GAT (single-pass softmax, warp per dst node) -------------------
__global__ void k_gat_node(int mod, int nNodes, int mode, float* __restrict__ out, int modoff) {
    int n = blockIdx.x * 8 + (threadIdx.x >> 5);
    if (n >= nNodes) return;
    float* xbase = g_xm + (size_t)mod * NN * D;
    int lane = threadIdx.x & 31;
    int beg = g_offG[n];
    int end = beg + g_degG[n];

    float2 xd = *(const float2*)&xbase[(size_t)n * D + lane * 2];

    float s = 0.f, ax = 0.f, ay = 0.f;
    for (int p = beg; p < end; p++) {
        int src = g_csrG_src[p];
        float2 v = *(const float2*)&xbase[(size_t)src * D + lane * 2];
        float dt = xd.x * v.x + xd.y * v.y;
        #pragma unroll
        for (int o = 16; o; o >>= 1) dt += __shfl_xor_sync(0xffffffffu, dt, o);
        float ex = __expf(dt);
        if (mode == 1 && lane == 0) g_e[p] = ex;
        s  += ex;
        ax += ex * v.x;
        ay += ex * v.y;
    }

    if (mode == 0) {
        float invs = 1.f / (s + 1e-16f);
        float nx = xd.x + ax * invs;
        float ny = xd.y + ay * invs;
        float ss = nx * nx + ny * ny;
        #pragma unroll
        for (int o = 16; o; o >>= 1) ss += __shfl_xor_sync(0xffffffffu, ss, o);
        float inv = rsqrtf(fmaxf(ss, 1e-24f));
        xbase[(size_t)n * D + lane * 2]     = nx * inv;
        xbase[(size_t)n * D + lane * 2 + 1] = ny * inv;
    } else {
        float inv2 = 1.f / (2.f * s + 1e-16f);
        float* alpha = g_alpha + (size_t)mod * E;
        __syncwarp();
        for (int p = beg + lane; p < end; p += 32)
            alpha[p] = g_e[p] * inv2;
        float sc = inv2 + inv2;
        int c = lane * 2;
        out[(size_t)n * OD + 64 + modoff + c]     = xd.x + lrelu(ax * sc);
        out[(size_t)n * OD + 64 + modoff + c + 1] = xd.y + lrelu(ay * sc);
    }
}

// Combined SAGE weight per CSR slot.
__global__ void k_weight(const float* __restrict__ conf) {
    int p = blockIdx.x * blockDim.x + threadIdx.x;
    if (p >= E) return;
    int src = g_csrG_src[p];
    float wv = g_alpha[p];
    float wt = g_alpha[E + p];
    float w = fmaxf(fmaxf(wv * conf[2 * src], wt * conf[2 * src + 1]), 0.f);
    g_wc[p] = w;
}

// SAGE gather over GAT CSR, warp per node.
__global__ void k_sage_node(int layer, float* __restrict__ out) {
    int n = blockIdx.x * 8 + (threadIdx.x >> 5);
    if (n >= NN) return;
    const float* xin = g_hx + (size_t)(layer - 1) * NN * D;
    int lane = threadIdx.x & 31;
    int beg = g_offG[n];
    int cnt = g_degG[n];
    float ax = 0.f, ay = 0.f;
    for (int p = beg; p < beg + cnt; p++) {
        float w = g_wc[p];
        if (w != 0.f) {
            int src = g_csrG_src[p];
            float2 v = *(const float2*)&xin[(size_t)src * D + lane * 2];
            ax += w * v.x;
            ay += w * v.y;
        }
    }
    float invd = 1.f / fmaxf((float)cnt, 1.f);
    float hx = lrelu(ax * invd), hy = lrelu(ay * invd);
    int c = lane * 2;
    if (layer == 1) {
        g_hx[(size_t)NN * D + (size_t)n * D + c]     = hx;
        g_hx[(size_t)NN * D + (size_t)n * D + c + 1] = hy;
    } else {
        size_t b = (size_t)n * D + c;
        out[(size_t)n * OD + c]     = g_hx[b]     + g_hx[(size_t)NN * D + b]     + hx;
        out[(size_t)n * OD + c + 1] = g_hx[b + 1] + g_hx[(size_t)NN * D + b + 1] + hy;
    }
}

// ------------------- launch -------------------
extern "C" void kernel_launch(void* const* d_in, const int* in_sizes, int n_in,
                              void* d_out, int out_size) {
    const void* ei = nullptr;
    const float *v_feat = 0, *t_feat = 0, *pref_v = 0, *pref_t = 0;
    const float *W_v = 0, *b_v = 0, *W_t = 0, *b_t = 0, *id_emb = 0, *conf = 0;
    for (int i = 0; i < n_in; i++) {
        long long sz = in_sizes[i];
        const void* p = d_in[i];
        switch (sz) {
            case 2000000LL:  ei = p; break;
            case 81920000LL: v_feat = (const float*)p; break;
            case 15360000LL: t_feat = (const float*)p; break;
            case 3200000LL:  if (!pref_v) pref_v = (const float*)p; else pref_t = (const float*)p; break;
            case 131072LL:   W_v = (const float*)p; break;
            case 24576LL:    W_t = (const float*)p; break;
            case 64LL:       if (!b_v) b_v = (const float*)p; else b_t = (const float*)p; break;
            case 5760000LL:  id_emb = (const float*)p; break;
            case 180000LL:   conf = (const float*)p; break;
            default: break;
        }
    }
    float* out = (float*)d_out;

    const int B = 256;
    const int gridNodeAll = divup(NN, 8);
    const int gridNodeU   = divup(NU, 8);
    const int nScanB      = divup(NN, 1024);

    k_sniff<<<1, 32>>>((const int*)ei);
    k_zero <<<divup(NN, B), B>>>();
    k_build<<<divup(E, B), B>>>(ei);
    k_scan1<<<nScanB, 1024>>>();
    k_scan2<<<1, 128>>>(nScanB);
    k_scan3<<<nScanB, 1024>>>();
    k_place<<<divup(E, B), B>>>();

    for (int mod = 0; mod < 2; mod++) {
        const float* feat_in = mod == 0 ? v_feat : t_feat;
        const float* W       = mod == 0 ? W_v : W_t;
        const float* bias    = mod == 0 ? b_v : b_t;
        const float* pref_in = mod == 0 ? pref_v : pref_t;
        int K = mod == 0 ? 2048 : 384;

        k_gemm_mma<<<divup(NI, 128), 256>>>(feat_in, W, bias, mod, K);
        k_l2norm_feat<<<divup(NI, 8), 256>>>(mod);
        k_l2norm_pref<<<divup(NU, 8), 256>>>(pref_in, mod);

        for (int it = 0; it < 3; it++)
            k_gat_node<<<gridNodeU, 256>>>(mod, NU, 0, nullptr, 0);

        k_gat_node<<<gridNodeAll, 256>>>(mod, NN, 1, out, mod * 64);
    }

    k_weight<<<divup(E, B), B>>>(conf);

    k_l2norm_x<<<divup(NN, 8), 256>>>(id_emb);
    k_sage_node<<<gridNodeAll, 256>>>(1, nullptr);
    k_sage_node<<<gridNodeAll, 256>>>(2, out);
}

// round 13
// speedup vs baseline: 1.0787x; 1.0787x over previous
#include <cuda_runtime.h>
#include <math.h>

#define NU 50000
#define NI 40000
#define NN 90000
#define D  64
#define EH 500000
#define E  1000000
#define OD 192

typedef unsigned long long ull;

// ------------------- scratch (static device globals; no allocation) -------------------
__device__ int   g_is64;
__device__ int   g_src[E];
__device__ int   g_dst[E];
__device__ int   g_degG[NN];
__device__ int   g_offG[NN];
__device__ int   g_curG[NN];
__device__ int   g_bsum[128];
__device__ int   g_csrG_src[E];
__device__ float g_e[2 * E];       // per-modality exp(logit)
__device__ float g_alpha[2 * E];
__device__ float g_wc[E];
__device__ __align__(16) float g_xm[2 * NN * D];
__device__ __align__(16) float g_hx[2 * NN * D];

__device__ __forceinline__ float lrelu(float v) { return v >= 0.f ? v : 0.01f * v; }
static inline int divup(int a, int b) { return (a + b - 1) / b; }

__device__ __forceinline__ void ffma2(ull& d, ull a, ull b) {
    asm("fma.rn.f32x2 %0, %1, %2, %0;" : "+l"(d) : "l"(a), "l"(b));
}
__device__ __forceinline__ ull pack2(float lo, float hi) {
    ull r;
    asm("mov.b64 %0, {%1, %2};" : "=l"(r) : "f"(lo), "f"(hi));
    return r;
}
__device__ __forceinline__ float2 unpack2(ull v) {
    float2 r;
    asm("mov.b64 {%0, %1}, %2;" : "=f"(r.x), "=f"(r.y) : "l"(v));
    return r;
}

// ------------------- edge dtype sniff -------------------
__global__ void k_sniff(const int* __restrict__ ei32) {
    int lane = threadIdx.x;
    int nz = 0;
    for (int i = lane; i < 512; i += 32)
        if (ei32[2 * i + 1] != 0) nz++;
    #pragma unroll
    for (int o = 16; o; o >>= 1) nz += __shfl_xor_sync(0xffffffffu, nz, o);
    if (lane == 0) g_is64 = (nz == 0) ? 1 : 0;
}

// ------------------- graph construction -------------------
__global__ void k_zero() {
    int i = blockIdx.x * blockDim.x + threadIdx.x;
    if (i < NN) g_degG[i] = 0;
}

__global__ void k_build(const void* __restrict__ eiRaw) {
    int i = blockIdx.x * blockDim.x + threadIdx.x;
    if (i >= E) return;
    int s, d;
    if (g_is64) {
        const long long* e64 = (const long long*)eiRaw;
        s = (int)e64[i];
        d = (int)e64[E + i];
    } else {
        const int* e32 = (const int*)eiRaw;
        s = e32[i];
        d = e32[E + i];
    }
    if ((unsigned)s >= NN) s = 0;
    if ((unsigned)d >= NN) d = 0;
    g_src[i] = s;
    g_dst[i] = d;
    atomicAdd(&g_degG[d], 1);
}

__global__ void k_scan1() {
    __shared__ int sh[1024];
    int t = threadIdx.x;
    int i = blockIdx.x * 1024 + t;
    int v = (i < NN) ? g_degG[i] : 0;
    sh[t] = v;
    __syncthreads();
    for (int st = 1; st < 1024; st <<= 1) {
        int x = (t >= st) ? sh[t - st] : 0;
        __syncthreads();
        sh[t] += x;
        __syncthreads();
    }
    if (i < NN) g_offG[i] = sh[t] - v;
    if (t == 1023) g_bsum[blockIdx.x] = sh[1023];
}

__global__ void k_scan2(int nb) {
    __shared__ int sh[128];
    int t = threadIdx.x;
    int v = (t < nb) ? g_bsum[t] : 0;
    sh[t] = v;
    __syncthreads();
    for (int st = 1; st < 128; st <<= 1) {
        int x = (t >= st) ? sh[t - st] : 0;
        __syncthreads();
        sh[t] += x;
        __syncthreads();
    }
    if (t < nb) g_bsum[t] = sh[t] - v;
}

__global__ void k_scan3() {
    int i = blockIdx.x * 1024 + threadIdx.x;
    if (i < NN) {
        int o = g_offG[i] + g_bsum[blockIdx.x];
        g_offG[i] = o;
        g_curG[i] = o;
    }
}

__global__ void k_place() {
    int i = blockIdx.x * blockDim.x + threadIdx.x;
    if (i >= E) return;
    int p = atomicAdd(&g_curG[g_dst[i]], 1);
    if ((unsigned)p < E) g_csrG_src[p] = g_src[i];
}

// ------------------- fused GEMM + bias + leaky + l2norm, both modalities -------------------
// blocks [0,GB): mod 0 (K=2048); [GB,2GB): mod 1 (K=384).
#define GB 313   // divup(NI,128)
__global__ __launch_bounds__(256) void k_gemm_both(
    const float* __restrict__ A0, const float* __restrict__ B0, const float* __restrict__ bias0,
    const float* __restrict__ A1, const float* __restrict__ B1, const float* __restrict__ bias1)
{
    int bid = blockIdx.x;
    int mod = (bid >= GB) ? 1 : 0;
    int mb  = mod ? (bid - GB) : bid;
    const float* A    = mod ? A1 : A0;
    const float* Bm   = mod ? B1 : B0;
    const float* bias = mod ? bias1 : bias0;
    int K = mod ? 384 : 2048;

    float* C = g_xm + (size_t)mod * NN * D + (size_t)NU * D;
    __shared__ __align__(16) float sA[32][132];
    __shared__ __align__(16) float sB[32][68];
    int t  = threadIdx.x;
    int tx = t & 15;
    int ty = t >> 4;
    int m0 = mb * 128;

    int ak4 = t & 7;
    int ar  = t >> 3;
    int bn4 = t & 15;
    int bkr = t >> 4;

    ull acc[4][4];
    #pragma unroll
    for (int i = 0; i < 4; i++)
        #pragma unroll
        for (int j = 0; j < 4; j++) acc[i][j] = 0ull;

    for (int kt = 0; kt < K; kt += 32) {
        #pragma unroll
        for (int p = 0; p < 4; p++) {
            int m = ar + p * 32;
            int gm = m0 + m;
            float4 av = make_float4(0.f, 0.f, 0.f, 0.f);
            if (gm < NI) av = *(const float4*)&A[(size_t)gm * K + kt + ak4 * 4];
            sA[ak4 * 4 + 0][m] = av.x;
            sA[ak4 * 4 + 1][m] = av.y;
            sA[ak4 * 4 + 2][m] = av.z;
            sA[ak4 * 4 + 3][m] = av.w;
        }
        #pragma unroll
        for (int p = 0; p < 2; p++) {
            int k = bkr + p * 16;
            *(float4*)&sB[k][bn4 * 4] = *(const float4*)&Bm[(size_t)(kt + k) * 64 + bn4 * 4];
        }
        __syncthreads();
        #pragma unroll
        for (int k = 0; k < 32; k++) {
            const ull* pa = (const ull*)&sA[k][ty * 8];
            ull a0 = pa[0], a1 = pa[1], a2 = pa[2], a3 = pa[3];
            float4 b = *(float4*)&sB[k][tx * 4];
            ull bs0 = pack2(b.x, b.x);
            ull bs1 = pack2(b.y, b.y);
            ull bs2 = pack2(b.z, b.z);
            ull bs3 = pack2(b.w, b.w);
            ffma2(acc[0][0], a0, bs0); ffma2(acc[0][1], a0, bs1); ffma2(acc[0][2], a0, bs2); ffma2(acc[0][3], a0, bs3);
            ffma2(acc[1][0], a1, bs0); ffma2(acc[1][1], a1, bs1); ffma2(acc[1][2], a1, bs2); ffma2(acc[1][3], a1, bs3);
            ffma2(acc[2][0], a2, bs0); ffma2(acc[2][1], a2, bs1); ffma2(acc[2][2], a2, bs2); ffma2(acc[2][3], a2, bs3);
            ffma2(acc[3][0], a3, bs0); ffma2(acc[3][1], a3, bs1); ffma2(acc[3][2], a3, bs2); ffma2(acc[3][3], a3, bs3);
        }
        __syncthreads();
    }

    float b4[4];
    #pragma unroll
    for (int j = 0; j < 4; j++) b4[j] = bias[tx * 4 + j];

    #pragma unroll
    for (int mp = 0; mp < 4; mp++) {
        float clo[4], chi[4];
        #pragma unroll
        for (int j = 0; j < 4; j++) {
            float2 v = unpack2(acc[mp][j]);
            clo[j] = lrelu(v.x + b4[j]);
            chi[j] = lrelu(v.y + b4[j]);
        }
        float sl  = clo[0]*clo[0] + clo[1]*clo[1] + clo[2]*clo[2] + clo[3]*clo[3];
        float sh2 = chi[0]*chi[0] + chi[1]*chi[1] + chi[2]*chi[2] + chi[3]*chi[3];
        #pragma unroll
        for (int o = 1; o < 16; o <<= 1) {
            sl  += __shfl_xor_sync(0xffffffffu, sl,  o);
            sh2 += __shfl_xor_sync(0xffffffffu, sh2, o);
        }
        float il = rsqrtf(fmaxf(sl,  1e-24f));
        float ih = rsqrtf(fmaxf(sh2, 1e-24f));
        int rl = m0 + ty * 8 + mp * 2;
        if (rl < NI) {
            float4 o4 = make_float4(clo[0]*il, clo[1]*il, clo[2]*il, clo[3]*il);
            *(float4*)&C[(size_t)rl * 64 + tx * 4] = o4;
        }
        if (rl + 1 < NI) {
            float4 o4 = make_float4(chi[0]*ih, chi[1]*ih, chi[2]*ih, chi[3]*ih);
            *(float4*)&C[(size_t)(rl + 1) * 64 + tx * 4] = o4;
        }
    }
}

// pref rows of xm[mod] = l2norm(input), mod = blockIdx.y.
__global__ void k_l2norm_pref(const float* __restrict__ in0, const float* __restrict__ in1) {
    int mod = blockIdx.y;
    const float* in = mod ? in1 : in0;
    int row = blockIdx.x * 8 + (threadIdx.x >> 5);
    if (row >= NU) return;
    float* p = g_xm + (size_t)mod * NN * D + (size_t)row * D;
    int lane = threadIdx.x & 31;
    float a = in[(size_t)row * 64 + lane];
    float b = in[(size_t)row * 64 + 32 + lane];
    float ss = a * a + b * b;
    #pragma unroll
    for (int o = 16; o; o >>= 1) ss += __shfl_xor_sync(0xffffffffu, ss, o);
    float inv = rsqrtf(fmaxf(ss, 1e-24f));
    p[lane]      = a * inv;
    p[32 + lane] = b * inv;
}

// g_hx slot0 = l2norm(id_emb) (NN rows).
__global__ void k_l2norm_x(const float* __restrict__ in) {
    int row = blockIdx.x * 8 + (threadIdx.x >> 5);
    if (row >= NN) return;
    int lane = threadIdx.x & 31;
    float a = in[(size_t)row * 64 + lane];
    float b = in[(size_t)row * 64 + 32 + lane];
    float ss = a * a + b * b;
    #pragma unroll
    for (int o = 16; o; o >>= 1) ss += __shfl_xor_sync(0xffffffffu, ss, o);
    float inv = rsqrtf(fmaxf(ss, 1e-24f));
    g_hx[(size_t)row * 64 + lane]      = a * inv;
    g_hx[(size_t)row * 64 + 32 + lane] = b * inv;
}

// ------------------- GAT (single-pass softmax, warp per dst node, mod = blockIdx.y) -------------------
__global__ void k_gat_node(int nNodes, int mode, float* __restrict__ out) {
    int n = blockIdx.x * 8 + (threadIdx.x >> 5);
    if (n >= nNodes) return;
    int mod = blockIdx.y;
    float* xbase = g_xm + (size_t)mod * NN * D;
    int lane = threadIdx.x & 31;
    int beg = g_offG[n];
    int end = beg + g_degG[n];

    float2 xd = *(const float2*)&xbase[(size_t)n * D + lane * 2];

    float* ebuf = g_e + (size_t)mod * E;
    float s = 0.f, ax = 0.f, ay = 0.f;
    for (int p = beg; p < end; p++) {
        int src = g_csrG_src[p];
        float2 v = *(const float2*)&xbase[(size_t)src * D + lane * 2];
        float dt = xd.x * v.x + xd.y * v.y;
        #pragma unroll
        for (int o = 16; o; o >>= 1) dt += __shfl_xor_sync(0xffffffffu, dt, o);
        float ex = __expf(dt);
        if (mode == 1 && lane == 0) ebuf[p] = ex;
        s  += ex;
        ax += ex * v.x;
        ay += ex * v.y;
    }

    if (mode == 0) {
        float invs = 1.f / (s + 1e-16f);
        float nx = xd.x + ax * invs;
        float ny = xd.y + ay * invs;
        float ss = nx * nx + ny * ny;
        #pragma unroll
        for (int o = 16; o; o >>= 1) ss += __shfl_xor_sync(0xffffffffu, ss, o);
        float inv = rsqrtf(fmaxf(ss, 1e-24f));
        xbase[(size_t)n * D + lane * 2]     = nx * inv;
        xbase[(size_t)n * D + lane * 2 + 1] = ny * inv;
    } else {
        float inv2 = 1.f / (2.f * s + 1e-16f);
        float* alpha = g_alpha + (size_t)mod * E;
        __syncwarp();
        for (int p = beg + lane; p < end; p += 32)
            alpha[p] = ebuf[p] * inv2;
        float sc = inv2 + inv2;
        int c = lane * 2;
        out[(size_t)n * OD + 64 + mod * 64 + c]     = xd.x + lrelu(ax * sc);
        out[(size_t)n * OD + 64 + mod * 64 + c + 1] = xd.y + lrelu(ay * sc);
    }
}

// Combined SAGE weight per CSR slot.
__global__ void k_weight(const float* __restrict__ conf) {
    int p = blockIdx.x * blockDim.x + threadIdx.x;
    if (p >= E) return;
    int src = g_csrG_src[p];
    float wv = g_alpha[p];
    float wt = g_alpha[E + p];
    float w = fmaxf(fmaxf(wv * conf[2 * src], wt * conf[2 * src + 1]), 0.f);
    g_wc[p] = w;
}

// SAGE gather over GAT CSR, warp per node.
__global__ void k_sage_node(int layer, float* __restrict__ out) {
    int n = blockIdx.x * 8 + (threadIdx.x >> 5);
    if (n >= NN) return;
    const float* xin = g_hx + (size_t)(layer - 1) * NN * D;
    int lane = threadIdx.x & 31;
    int beg = g_offG[n];
    int cnt = g_degG[n];
    float ax = 0.f, ay = 0.f;
    for (int p = beg; p < beg + cnt; p++) {
        float w = g_wc[p];
        if (w != 0.f) {
            int src = g_csrG_src[p];
            float2 v = *(const float2*)&xin[(size_t)src * D + lane * 2];
            ax += w * v.x;
            ay += w * v.y;
        }
    }
    float invd = 1.f / fmaxf((float)cnt, 1.f);
    float hx = lrelu(ax * invd), hy = lrelu(ay * invd);
    int c = lane * 2;
    if (layer == 1) {
        g_hx[(size_t)NN * D + (size_t)n * D + c]     = hx;
        g_hx[(size_t)NN * D + (size_t)n * D + c + 1] = hy;
    } else {
        size_t b = (size_t)n * D + c;
        out[(size_t)n * OD + c]     = g_hx[b]     + g_hx[(size_t)NN * D + b]     + hx;
        out[(size_t)n * OD + c + 1] = g_hx[b + 1] + g_hx[(size_t)NN * D + b + 1] + hy;
    }
}

// ------------------- launch -------------------
extern "C" void kernel_launch(void* const* d_in, const int* in_sizes, int n_in,
                              void* d_out, int out_size) {
    const void* ei = nullptr;
    const float *v_feat = 0, *t_feat = 0, *pref_v = 0, *pref_t = 0;
    const float *W_v = 0, *b_v = 0, *W_t = 0, *b_t = 0, *id_emb = 0, *conf = 0;
    for (int i = 0; i < n_in; i++) {
        long long sz = in_sizes[i];
        const void* p = d_in[i];
        switch (sz) {
            case 2000000LL:  ei = p; break;
            case 81920000LL: v_feat = (const float*)p; break;
            case 15360000LL: t_feat = (const float*)p; break;
            case 3200000LL:  if (!pref_v) pref_v = (const float*)p; else pref_t = (const float*)p; break;
            case 131072LL:   W_v = (const float*)p; break;
            case 24576LL:    W_t = (const float*)p; break;
            case 64LL:       if (!b_v) b_v = (const float*)p; else b_t = (const float*)p; break;
            case 5760000LL:  id_emb = (const float*)p; break;
            case 180000LL:   conf = (const float*)p; break;
            default: break;
        }
    }
    float* out = (float*)d_out;

    const int B = 256;
    const int nScanB = divup(NN, 1024);
    dim3 gU(divup(NU, 8), 2);
    dim3 gA(divup(NN, 8), 2);

    // graph construction
    k_sniff<<<1, 32>>>((const int*)ei);
    k_zero <<<divup(NN, B), B>>>();
    k_build<<<divup(E, B), B>>>(ei);
    k_scan1<<<nScanB, 1024>>>();
    k_scan2<<<1, 128>>>(nScanB);
    k_scan3<<<nScanB, 1024>>>();
    k_place<<<divup(E, B), B>>>();

    // both content branches, batched
    k_gemm_both<<<2 * GB, 256>>>(v_feat, W_v, b_v, t_feat, W_t, b_t);
    k_l2norm_pref<<<gU, 256>>>(pref_v, pref_t);
    k_l2norm_x<<<divup(NN, 8), 256>>>(id_emb);

    for (int it = 0; it < 3; it++)
        k_gat_node<<<gU, 256>>>(NU, 0, nullptr);
    k_gat_node<<<gA, 256>>>(NN, 1, out);

    // SAGE
    k_weight<<<divup(E, B), B>>>(conf);
    k_sage_node<<<divup(NN, 8), 256>>>(1, nullptr);
    k_sage_node<<<divup(NN, 8), 256>>>(2, out);
}

// round 14
// speedup vs baseline: 1.1382x; 1.0552x over previous
#include <cuda_runtime.h>
#include <math.h>

#define NU 50000
#define NI 40000
#define NN 90000
#define D  64
#define EH 500000
#define E  1000000
#define OD 192

typedef unsigned long long ull;

// ------------------- scratch (static device globals; no allocation) -------------------
__device__ int   g_is64;
__device__ int   g_src[E];
__device__ int   g_dst[E];
__device__ int   g_degG[NN];
__device__ int   g_offG[NN];
__device__ int   g_curG[NN];
__device__ int   g_bsum[128];
__device__ int   g_csrG_src[E];
__device__ float g_e[2 * E];       // per-modality exp(logit)
__device__ float g_alpha[2 * E];
__device__ float g_wc[E];
__device__ __align__(16) float g_xm[2 * NN * D];
__device__ __align__(16) float g_hx[2 * NN * D];

__device__ __forceinline__ float lrelu(float v) { return v >= 0.f ? v : 0.01f * v; }
static inline int divup(int a, int b) { return (a + b - 1) / b; }

__device__ __forceinline__ void ffma2(ull& d, ull a, ull b) {
    asm("fma.rn.f32x2 %0, %1, %2, %0;" : "+l"(d) : "l"(a), "l"(b));
}
__device__ __forceinline__ ull pack2(float lo, float hi) {
    ull r;
    asm("mov.b64 %0, {%1, %2};" : "=l"(r) : "f"(lo), "f"(hi));
    return r;
}
__device__ __forceinline__ float2 unpack2(ull v) {
    float2 r;
    asm("mov.b64 {%0, %1}, %2;" : "=f"(r.x), "=f"(r.y) : "l"(v));
    return r;
}

// ------------------- edge dtype sniff -------------------
__global__ void k_sniff(const int* __restrict__ ei32) {
    int lane = threadIdx.x;
    int nz = 0;
    for (int i = lane; i < 512; i += 32)
        if (ei32[2 * i + 1] != 0) nz++;
    #pragma unroll
    for (int o = 16; o; o >>= 1) nz += __shfl_xor_sync(0xffffffffu, nz, o);
    if (lane == 0) g_is64 = (nz == 0) ? 1 : 0;
}

// ------------------- graph construction -------------------
__global__ void k_zero() {
    int i = blockIdx.x * blockDim.x + threadIdx.x;
    if (i < NN) g_degG[i] = 0;
}

__global__ void k_build(const void* __restrict__ eiRaw) {
    int i = blockIdx.x * blockDim.x + threadIdx.x;
    if (i >= E) return;
    int s, d;
    if (g_is64) {
        const long long* e64 = (const long long*)eiRaw;
        s = (int)e64[i];
        d = (int)e64[E + i];
    } else {
        const int* e32 = (const int*)eiRaw;
        s = e32[i];
        d = e32[E + i];
    }
    if ((unsigned)s >= NN) s = 0;
    if ((unsigned)d >= NN) d = 0;
    g_src[i] = s;
    g_dst[i] = d;
    atomicAdd(&g_degG[d], 1);
}

__global__ void k_scan1() {
    __shared__ int sh[1024];
    int t = threadIdx.x;
    int i = blockIdx.x * 1024 + t;
    int v = (i < NN) ? g_degG[i] : 0;
    sh[t] = v;
    __syncthreads();
    for (int st = 1; st < 1024; st <<= 1) {
        int x = (t >= st) ? sh[t - st] : 0;
        __syncthreads();
        sh[t] += x;
        __syncthreads();
    }
    if (i < NN) g_offG[i] = sh[t] - v;
    if (t == 1023) g_bsum[blockIdx.x] = sh[1023];
}

__global__ void k_scan2(int nb) {
    __shared__ int sh[128];
    int t = threadIdx.x;
    int v = (t < nb) ? g_bsum[t] : 0;
    sh[t] = v;
    __syncthreads();
    for (int st = 1; st < 128; st <<= 1) {
        int x = (t >= st) ? sh[t - st] : 0;
        __syncthreads();
        sh[t] += x;
        __syncthreads();
    }
    if (t < nb) g_bsum[t] = sh[t] - v;
}

__global__ void k_scan3() {
    int i = blockIdx.x * 1024 + threadIdx.x;
    if (i < NN) {
        int o = g_offG[i] + g_bsum[blockIdx.x];
        g_offG[i] = o;
        g_curG[i] = o;
    }
}

__global__ void k_place() {
    int i = blockIdx.x * blockDim.x + threadIdx.x;
    if (i >= E) return;
    int p = atomicAdd(&g_curG[g_dst[i]], 1);
    if ((unsigned)p < E) g_csrG_src[p] = g_src[i];
}

// ------------------- fused GEMM (double-buffered) + bias + leaky + l2norm -------------------
#define GB 313   // divup(NI,128)
__global__ __launch_bounds__(256) void k_gemm_both(
    const float* __restrict__ A0, const float* __restrict__ B0, const float* __restrict__ bias0,
    const float* __restrict__ A1, const float* __restrict__ B1, const float* __restrict__ bias1)
{
    int bid = blockIdx.x;
    int mod = (bid >= GB) ? 1 : 0;
    int mb  = mod ? (bid - GB) : bid;
    const float* A    = mod ? A1 : A0;
    const float* Bm   = mod ? B1 : B0;
    const float* bias = mod ? bias1 : bias0;
    int K = mod ? 384 : 2048;

    float* C = g_xm + (size_t)mod * NN * D + (size_t)NU * D;
    __shared__ __align__(16) float sA[32][132];
    __shared__ __align__(16) float sB[32][68];
    int t  = threadIdx.x;
    int tx = t & 15;
    int ty = t >> 4;
    int m0 = mb * 128;

    int ak4 = t & 7;
    int ar  = t >> 3;
    int bn4 = t & 15;
    int bkr = t >> 4;

    ull acc[4][4];
    #pragma unroll
    for (int i = 0; i < 4; i++)
        #pragma unroll
        for (int j = 0; j < 4; j++) acc[i][j] = 0ull;

    float4 avr[4], bvr[2];
    // prologue: stage tile 0
    #pragma unroll
    for (int p = 0; p < 4; p++) {
        int gm = m0 + ar + p * 32;
        avr[p] = make_float4(0.f, 0.f, 0.f, 0.f);
        if (gm < NI) avr[p] = *(const float4*)&A[(size_t)gm * K + ak4 * 4];
    }
    #pragma unroll
    for (int p = 0; p < 2; p++)
        bvr[p] = *(const float4*)&Bm[(size_t)(bkr + p * 16) * 64 + bn4 * 4];

    for (int kt = 0; kt < K; kt += 32) {
        // staged regs -> smem
        #pragma unroll
        for (int p = 0; p < 4; p++) {
            int m = ar + p * 32;
            sA[ak4 * 4 + 0][m] = avr[p].x;
            sA[ak4 * 4 + 1][m] = avr[p].y;
            sA[ak4 * 4 + 2][m] = avr[p].z;
            sA[ak4 * 4 + 3][m] = avr[p].w;
        }
        #pragma unroll
        for (int p = 0; p < 2; p++)
            *(float4*)&sB[bkr + p * 16][bn4 * 4] = bvr[p];
        __syncthreads();

        // prefetch next tile into regs (overlaps with compute below)
        if (kt + 32 < K) {
            #pragma unroll
            for (int p = 0; p < 4; p++) {
                int gm = m0 + ar + p * 32;
                avr[p] = make_float4(0.f, 0.f, 0.f, 0.f);
                if (gm < NI) avr[p] = *(const float4*)&A[(size_t)gm * K + kt + 32 + ak4 * 4];
            }
            #pragma unroll
            for (int p = 0; p < 2; p++)
                bvr[p] = *(const float4*)&Bm[(size_t)(kt + 32 + bkr + p * 16) * 64 + bn4 * 4];
        }

        #pragma unroll
        for (int k = 0; k < 32; k++) {
            const ull* pa = (const ull*)&sA[k][ty * 8];
            ull a0 = pa[0], a1 = pa[1], a2 = pa[2], a3 = pa[3];
            float4 b = *(float4*)&sB[k][tx * 4];
            ull bs0 = pack2(b.x, b.x);
            ull bs1 = pack2(b.y, b.y);
            ull bs2 = pack2(b.z, b.z);
            ull bs3 = pack2(b.w, b.w);
            ffma2(acc[0][0], a0, bs0); ffma2(acc[0][1], a0, bs1); ffma2(acc[0][2], a0, bs2); ffma2(acc[0][3], a0, bs3);
            ffma2(acc[1][0], a1, bs0); ffma2(acc[1][1], a1, bs1); ffma2(acc[1][2], a1, bs2); ffma2(acc[1][3], a1, bs3);
            ffma2(acc[2][0], a2, bs0); ffma2(acc[2][1], a2, bs1); ffma2(acc[2][2], a2, bs2); ffma2(acc[2][3], a2, bs3);
            ffma2(acc[3][0], a3, bs0); ffma2(acc[3][1], a3, bs1); ffma2(acc[3][2], a3, bs2); ffma2(acc[3][3], a3, bs3);
        }
        __syncthreads();
    }

    float b4[4];
    #pragma unroll
    for (int j = 0; j < 4; j++) b4[j] = bias[tx * 4 + j];

    #pragma unroll
    for (int mp = 0; mp < 4; mp++) {
        float clo[4], chi[4];
        #pragma unroll
        for (int j = 0; j < 4; j++) {
            float2 v = unpack2(acc[mp][j]);
            clo[j] = lrelu(v.x + b4[j]);
            chi[j] = lrelu(v.y + b4[j]);
        }
        float sl  = clo[0]*clo[0] + clo[1]*clo[1] + clo[2]*clo[2] + clo[3]*clo[3];
        float sh2 = chi[0]*chi[0] + chi[1]*chi[1] + chi[2]*chi[2] + chi[3]*chi[3];
        #pragma unroll
        for (int o = 1; o < 16; o <<= 1) {
            sl  += __shfl_xor_sync(0xffffffffu, sl,  o);
            sh2 += __shfl_xor_sync(0xffffffffu, sh2, o);
        }
        float il = rsqrtf(fmaxf(sl,  1e-24f));
        float ih = rsqrtf(fmaxf(sh2, 1e-24f));
        int rl = m0 + ty * 8 + mp * 2;
        if (rl < NI) {
            float4 o4 = make_float4(clo[0]*il, clo[1]*il, clo[2]*il, clo[3]*il);
            *(float4*)&C[(size_t)rl * 64 + tx * 4] = o4;
        }
        if (rl + 1 < NI) {
            float4 o4 = make_float4(chi[0]*ih, chi[1]*ih, chi[2]*ih, chi[3]*ih);
            *(float4*)&C[(size_t)(rl + 1) * 64 + tx * 4] = o4;
        }
    }
}

// pref rows of xm[mod] = l2norm(input), mod = blockIdx.y.
__global__ void k_l2norm_pref(const float* __restrict__ in0, const float* __restrict__ in1) {
    int mod = blockIdx.y;
    const float* in = mod ? in1 : in0;
    int row = blockIdx.x * 8 + (threadIdx.x >> 5);
    if (row >= NU) return;
    float* p = g_xm + (size_t)mod * NN * D + (size_t)row * D;
    int lane = threadIdx.x & 31;
    float a = in[(size_t)row * 64 + lane];
    float b = in[(size_t)row * 64 + 32 + lane];
    float ss = a * a + b * b;
    #pragma unroll
    for (int o = 16; o; o >>= 1) ss += __shfl_xor_sync(0xffffffffu, ss, o);
    float inv = rsqrtf(fmaxf(ss, 1e-24f));
    p[lane]      = a * inv;
    p[32 + lane] = b * inv;
}

// g_hx slot0 = l2norm(id_emb) (NN rows).
__global__ void k_l2norm_x(const float* __restrict__ in) {
    int row = blockIdx.x * 8 + (threadIdx.x >> 5);
    if (row >= NN) return;
    int lane = threadIdx.x & 31;
    float a = in[(size_t)row * 64 + lane];
    float b = in[(size_t)row * 64 + 32 + lane];
    float ss = a * a + b * b;
    #pragma unroll
    for (int o = 16; o; o >>= 1) ss += __shfl_xor_sync(0xffffffffu, ss, o);
    float inv = rsqrtf(fmaxf(ss, 1e-24f));
    g_hx[(size_t)row * 64 + lane]      = a * inv;
    g_hx[(size_t)row * 64 + 32 + lane] = b * inv;
}

// ------------------- GAT (single-pass softmax, chunked MLP=4 gather) -------------------
__global__ void k_gat_node(int nNodes, int mode, float* __restrict__ out) {
    int n = blockIdx.x * 8 + (threadIdx.x >> 5);
    if (n >= nNodes) return;
    int mod = blockIdx.y;
    float* xbase = g_xm + (size_t)mod * NN * D;
    int lane = threadIdx.x & 31;
    int beg = g_offG[n];
    int end = beg + g_degG[n];

    float2 xd = *(const float2*)&xbase[(size_t)n * D + lane * 2];

    float* ebuf = g_e + (size_t)mod * E;
    float s = 0.f, ax = 0.f, ay = 0.f;
    for (int p0 = beg; p0 < end; p0 += 4) {
        int cnt = end - p0;
        if (cnt > 4) cnt = 4;
        float2 vv[4];
        int sidx[4];
        #pragma unroll
        for (int j = 0; j < 4; j++)
            if (j < cnt) sidx[j] = g_csrG_src[p0 + j];
        #pragma unroll
        for (int j = 0; j < 4; j++)
            if (j < cnt) vv[j] = *(const float2*)&xbase[(size_t)sidx[j] * D + lane * 2];
        #pragma unroll
        for (int j = 0; j < 4; j++) {
            if (j < cnt) {
                float dt = xd.x * vv[j].x + xd.y * vv[j].y;
                #pragma unroll
                for (int o = 16; o; o >>= 1) dt += __shfl_xor_sync(0xffffffffu, dt, o);
                float ex = __expf(dt);
                if (mode == 1 && lane == 0) ebuf[p0 + j] = ex;
                s  += ex;
                ax += ex * vv[j].x;
                ay += ex * vv[j].y;
            }
        }
    }

    if (mode == 0) {
        float invs = 1.f / (s + 1e-16f);
        float nx = xd.x + ax * invs;
        float ny = xd.y + ay * invs;
        float ss = nx * nx + ny * ny;
        #pragma unroll
        for (int o = 16; o; o >>= 1) ss += __shfl_xor_sync(0xffffffffu, ss, o);
        float inv = rsqrtf(fmaxf(ss, 1e-24f));
        xbase[(size_t)n * D + lane * 2]     = nx * inv;
        xbase[(size_t)n * D + lane * 2 + 1] = ny * inv;
    } else {
        float inv2 = 1.f / (2.f * s + 1e-16f);
        float* alpha = g_alpha + (size_t)mod * E;
        __syncwarp();
        for (int p = beg + lane; p < end; p += 32)
            alpha[p] = ebuf[p] * inv2;
        float sc = inv2 + inv2;
        int c = lane * 2;
        out[(size_t)n * OD + 64 + mod * 64 + c]     = xd.x + lrelu(ax * sc);
        out[(size_t)n * OD + 64 + mod * 64 + c + 1] = xd.y + lrelu(ay * sc);
    }
}

// SAGE gather (chunked). layer 1 computes g_wc inline (each slot visited once) and
// writes h1; layer 2 reads g_wc and writes out[:,0:64] = x + h1 + h2.
__global__ void k_sage_node(int layer, const float* __restrict__ conf, float* __restrict__ out) {
    int n = blockIdx.x * 8 + (threadIdx.x >> 5);
    if (n >= NN) return;
    const float* xin = g_hx + (size_t)(layer - 1) * NN * D;
    int lane = threadIdx.x & 31;
    int beg = g_offG[n];
    int cnt0 = g_degG[n];
    int end = beg + cnt0;
    float ax = 0.f, ay = 0.f;

    for (int p0 = beg; p0 < end; p0 += 4) {
        int cnt = end - p0;
        if (cnt > 4) cnt = 4;
        int sidx[4];
        float w[4];
        #pragma unroll
        for (int j = 0; j < 4; j++)
            if (j < cnt) sidx[j] = g_csrG_src[p0 + j];
        if (layer == 1) {
            #pragma unroll
            for (int j = 0; j < 4; j++)
                if (j < cnt) {
                    float wv = g_alpha[p0 + j];
                    float wt = g_alpha[E + p0 + j];
                    float2 cf = *(const float2*)&conf[2 * sidx[j]];
                    w[j] = fmaxf(fmaxf(wv * cf.x, wt * cf.y), 0.f);
                    if (lane == 0) g_wc[p0 + j] = w[j];
                }
        } else {
            #pragma unroll
            for (int j = 0; j < 4; j++)
                if (j < cnt) w[j] = g_wc[p0 + j];
        }
        float2 vv[4];
        #pragma unroll
        for (int j = 0; j < 4; j++)
            if (j < cnt && w[j] != 0.f)
                vv[j] = *(const float2*)&xin[(size_t)sidx[j] * D + lane * 2];
        #pragma unroll
        for (int j = 0; j < 4; j++)
            if (j < cnt && w[j] != 0.f) {
                ax += w[j] * vv[j].x;
                ay += w[j] * vv[j].y;
            }
    }

    float invd = 1.f / fmaxf((float)cnt0, 1.f);
    float hx = lrelu(ax * invd), hy = lrelu(ay * invd);
    int c = lane * 2;
    if (layer == 1) {
        g_hx[(size_t)NN * D + (size_t)n * D + c]     = hx;
        g_hx[(size_t)NN * D + (size_t)n * D + c + 1] = hy;
    } else {
        size_t b = (size_t)n * D + c;
        out[(size_t)n * OD + c]     = g_hx[b]     + g_hx[(size_t)NN * D + b]     + hx;
        out[(size_t)n * OD + c + 1] = g_hx[b + 1] + g_hx[(size_t)NN * D + b + 1] + hy;
    }
}

// ------------------- launch -------------------
extern "C" void kernel_launch(void* const* d_in, const int* in_sizes, int n_in,
                              void* d_out, int out_size) {
    const void* ei = nullptr;
    const float *v_feat = 0, *t_feat = 0, *pref_v = 0, *pref_t = 0;
    const float *W_v = 0, *b_v = 0, *W_t = 0, *b_t = 0, *id_emb = 0, *conf = 0;
    for (int i = 0; i < n_in; i++) {
        long long sz = in_sizes[i];
        const void* p = d_in[i];
        switch (sz) {
            case 2000000LL:  ei = p; break;
            case 81920000LL: v_feat = (const float*)p; break;
            case 15360000LL: t_feat = (const float*)p; break;
            case 3200000LL:  if (!pref_v) pref_v = (const float*)p; else pref_t = (const float*)p; break;
            case 131072LL:   W_v = (const float*)p; break;
            case 24576LL:    W_t = (const float*)p; break;
            case 64LL:       if (!b_v) b_v = (const float*)p; else b_t = (const float*)p; break;
            case 5760000LL:  id_emb = (const float*)p; break;
            case 180000LL:   conf = (const float*)p; break;
            default: break;
        }
    }
    float* out = (float*)d_out;

    const int B = 256;
    const int nScanB = divup(NN, 1024);
    dim3 gU(divup(NU, 8), 2);
    dim3 gA(divup(NN, 8), 2);

    // graph construction
    k_sniff<<<1, 32>>>((const int*)ei);
    k_zero <<<divup(NN, B), B>>>();
    k_build<<<divup(E, B), B>>>(ei);
    k_scan1<<<nScanB, 1024>>>();
    k_scan2<<<1, 128>>>(nScanB);
    k_scan3<<<nScanB, 1024>>>();
    k_place<<<divup(E, B), B>>>();

    // both content branches, batched
    k_gemm_both<<<2 * GB, 256>>>(v_feat, W_v, b_v, t_feat, W_t, b_t);
    k_l2norm_pref<<<gU, 256>>>(pref_v, pref_t);
    k_l2norm_x<<<divup(NN, 8), 256>>>(id_emb);

    for (int it = 0; it < 3; it++)
        k_gat_node<<<gU, 256>>>(NU, 0, nullptr);
    k_gat_node<<<gA, 256>>>(NN, 1, out);

    // SAGE (layer 1 computes edge weights inline)
    k_sage_node<<<divup(NN, 8), 256>>>(1, conf, nullptr);
    k_sage_node<<<divup(NN, 8), 256>>>(2, conf, out);
}

// round 15
// speedup vs baseline: 1.3150x; 1.1553x over previous
#include <cuda_runtime.h>
#include <cuda_bf16.h>
#include <math.h>

#define NU 50000
#define NI 40000
#define NN 90000
#define D  64
#define EH 500000
#define E  1000000
#define OD 192

typedef unsigned int uint;

// ------------------- scratch (static device globals; no allocation) -------------------
__device__ int   g_is64;
__device__ int   g_src[E];
__device__ int   g_dst[E];
__device__ int   g_degG[NN];
__device__ int   g_offG[NN];
__device__ int   g_curG[NN];
__device__ int   g_bsum[128];
__device__ int   g_csrG_src[E];
__device__ float g_e[2 * E];
__device__ float g_alpha[2 * E];
__device__ float g_wc[E];
__device__ __align__(16) float g_xm[2 * NN * D];
__device__ __align__(16) float g_hx[2 * NN * D];

__device__ __forceinline__ float lrelu(float v) { return v >= 0.f ? v : 0.01f * v; }
static inline int divup(int a, int b) { return (a + b - 1) / b; }

// ------------------- tensor helpers -------------------
__device__ __forceinline__ uint smem_u32(const void* p) {
    return (uint)__cvta_generic_to_shared(p);
}
__device__ __forceinline__ void ldsm4(uint& r0, uint& r1, uint& r2, uint& r3, uint addr) {
    asm volatile("ldmatrix.sync.aligned.m8n8.x4.shared.b16 {%0,%1,%2,%3},[%4];"
        : "=r"(r0), "=r"(r1), "=r"(r2), "=r"(r3) : "r"(addr));
}
__device__ __forceinline__ void ldsm4t(uint& r0, uint& r1, uint& r2, uint& r3, uint addr) {
    asm volatile("ldmatrix.sync.aligned.m8n8.x4.trans.shared.b16 {%0,%1,%2,%3},[%4];"
        : "=r"(r0), "=r"(r1), "=r"(r2), "=r"(r3) : "r"(addr));
}
__device__ __forceinline__ void mma_bf16(float* c, const uint* a, const uint* b) {
    asm volatile("mma.sync.aligned.m16n8k16.row.col.f32.bf16.bf16.f32 "
        "{%0,%1,%2,%3},{%4,%5,%6,%7},{%8,%9},{%0,%1,%2,%3};"
        : "+f"(c[0]), "+f"(c[1]), "+f"(c[2]), "+f"(c[3])
        : "r"(a[0]), "r"(a[1]), "r"(a[2]), "r"(a[3]), "r"(b[0]), "r"(b[1]));
}
__device__ __forceinline__ void cvt_split(float v, __nv_bfloat16& h, __nv_bfloat16& l) {
    h = __float2bfloat16_rn(v);
    l = __float2bfloat16_rn(v - __bfloat162float(h));
}

// ------------------- edge dtype sniff -------------------
__global__ void k_sniff(const int* __restrict__ ei32) {
    int lane = threadIdx.x;
    int nz = 0;
    for (int i = lane; i < 512; i += 32)
        if (ei32[2 * i + 1] != 0) nz++;
    #pragma unroll
    for (int o = 16; o; o >>= 1) nz += __shfl_xor_sync(0xffffffffu, nz, o);
    if (lane == 0) g_is64 = (nz == 0) ? 1 : 0;
}

// ------------------- graph construction -------------------
__global__ void k_zero() {
    int i = blockIdx.x * blockDim.x + threadIdx.x;
    if (i < NN) g_degG[i] = 0;
}

__global__ void k_build(const void* __restrict__ eiRaw) {
    int i = blockIdx.x * blockDim.x + threadIdx.x;
    if (i >= E) return;
    int s, d;
    if (g_is64) {
        const long long* e64 = (const long long*)eiRaw;
        s = (int)e64[i];
        d = (int)e64[E + i];
    } else {
        const int* e32 = (const int*)eiRaw;
        s = e32[i];
        d = e32[E + i];
    }
    if ((unsigned)s >= NN) s = 0;
    if ((unsigned)d >= NN) d = 0;
    g_src[i] = s;
    g_dst[i] = d;
    atomicAdd(&g_degG[d], 1);
}

__global__ void k_scan1() {
    __shared__ int sh[1024];
    int t = threadIdx.x;
    int i = blockIdx.x * 1024 + t;
    int v = (i < NN) ? g_degG[i] : 0;
    sh[t] = v;
    __syncthreads();
    for (int st = 1; st < 1024; st <<= 1) {
        int x = (t >= st) ? sh[t - st] : 0;
        __syncthreads();
        sh[t] += x;
        __syncthreads();
    }
    if (i < NN) g_offG[i] = sh[t] - v;
    if (t == 1023) g_bsum[blockIdx.x] = sh[1023];
}

__global__ void k_scan2(int nb) {
    __shared__ int sh[128];
    int t = threadIdx.x;
    int v = (t < nb) ? g_bsum[t] : 0;
    sh[t] = v;
    __syncthreads();
    for (int st = 1; st < 128; st <<= 1) {
        int x = (t >= st) ? sh[t - st] : 0;
        __syncthreads();
        sh[t] += x;
        __syncthreads();
    }
    if (t < nb) g_bsum[t] = sh[t] - v;
}

__global__ void k_scan3() {
    int i = blockIdx.x * 1024 + threadIdx.x;
    if (i < NN) {
        int o = g_offG[i] + g_bsum[blockIdx.x];
        g_offG[i] = o;
        g_curG[i] = o;
    }
}

__global__ void k_place() {
    int i = blockIdx.x * blockDim.x + threadIdx.x;
    if (i >= E) return;
    int p = atomicAdd(&g_curG[g_dst[i]], 1);
    if ((unsigned)p < E) g_csrG_src[p] = g_src[i];
}

// ------------------- bf16-split tensor-core GEMM + bias + leaky -------------------
// C = leaky(A @ W + bias). Block tile 128x64, K-tile 32, 8 warps (4m x 2n, warp 32x32).
// A,W split once per tile into bf16 hi/lo; 3 mma passes: h*h + l*h + h*l.
#define GB 313   // divup(NI,128)
__global__ __launch_bounds__(256) void k_gemm_both(
    const float* __restrict__ A0, const float* __restrict__ B0, const float* __restrict__ bias0,
    const float* __restrict__ A1, const float* __restrict__ B1, const float* __restrict__ bias1)
{
    int bid = blockIdx.x;
    int mod = (bid >= GB) ? 1 : 0;
    int mb  = mod ? (bid - GB) : bid;
    const float* A    = mod ? A1 : A0;
    const float* Bm   = mod ? B1 : B0;
    const float* bias = mod ? bias1 : bias0;
    int K = mod ? 384 : 2048;

    float* C = g_xm + (size_t)mod * NN * D + (size_t)NU * D;
    __shared__ __nv_bfloat16 sAh[128][40];   // stride 40 bf16 = 80B: conflict-free ldmatrix
    __shared__ __nv_bfloat16 sAl[128][40];
    __shared__ __nv_bfloat16 sBh[32][72];    // stride 72 bf16 = 144B: conflict-free trans ldmatrix
    __shared__ __nv_bfloat16 sBl[32][72];

    int t    = threadIdx.x;
    int lane = t & 31;
    int wid  = t >> 5;
    int mw   = (wid & 3) * 32;
    int nw   = (wid >> 2) * 32;
    int m0   = mb * 128;

    // loader indices
    int la_r = t >> 3;            // 0..31 (+p*32)
    int la_c = (t & 7) * 4;       // k col group
    int lb_k = t >> 4;            // 0..15 (+16)
    int lb_c = (t & 15) * 4;      // n col group

    // ldmatrix lane addressing
    int lr  = lane & 7;
    int sel = lane >> 3;

    float c[2][4][4];
    #pragma unroll
    for (int i = 0; i < 2; i++)
        #pragma unroll
        for (int j = 0; j < 4; j++)
            #pragma unroll
            for (int q = 0; q < 4; q++) c[i][j][q] = 0.f;

    float4 avr[4], bvr[2];
    #pragma unroll
    for (int p = 0; p < 4; p++) {
        int gm = m0 + la_r + p * 32;
        avr[p] = make_float4(0.f, 0.f, 0.f, 0.f);
        if (gm < NI) avr[p] = *(const float4*)&A[(size_t)gm * K + la_c];
    }
    #pragma unroll
    for (int p = 0; p < 2; p++)
        bvr[p] = *(const float4*)&Bm[(size_t)(lb_k + p * 16) * 64 + lb_c];

    for (int kt = 0; kt < K; kt += 32) {
        // split + store staged tile
        #pragma unroll
        for (int p = 0; p < 4; p++) {
            int m = la_r + p * 32;
            float vv[4] = {avr[p].x, avr[p].y, avr[p].z, avr[p].w};
            #pragma unroll
            for (int j = 0; j < 4; j++) {
                __nv_bfloat16 h, l;
                cvt_split(vv[j], h, l);
                sAh[m][la_c + j] = h;
                sAl[m][la_c + j] = l;
            }
        }
        #pragma unroll
        for (int p = 0; p < 2; p++) {
            int k = lb_k + p * 16;
            float vv[4] = {bvr[p].x, bvr[p].y, bvr[p].z, bvr[p].w};
            #pragma unroll
            for (int j = 0; j < 4; j++) {
                __nv_bfloat16 h, l;
                cvt_split(vv[j], h, l);
                sBh[k][lb_c + j] = h;
                sBl[k][lb_c + j] = l;
            }
        }
        __syncthreads();

        // prefetch next tile
        if (kt + 32 < K) {
            #pragma unroll
            for (int p = 0; p < 4; p++) {
                int gm = m0 + la_r + p * 32;
                avr[p] = make_float4(0.f, 0.f, 0.f, 0.f);
                if (gm < NI) avr[p] = *(const float4*)&A[(size_t)gm * K + kt + 32 + la_c];
            }
            #pragma unroll
            for (int p = 0; p < 2; p++)
                bvr[p] = *(const float4*)&Bm[(size_t)(kt + 32 + lb_k + p * 16) * 64 + lb_c];
        }

        #pragma unroll
        for (int kk = 0; kk < 32; kk += 16) {
            // B fragments: 4 n8-tiles, hi+lo (trans ldmatrix, 2 n-tiles per x4)
            uint bh[4][2], bl[4][2];
            #pragma unroll
            for (int np = 0; np < 2; np++) {
                int brow = kk + lr + (sel & 1) * 8;
                int bcol = nw + np * 16 + (sel >> 1) * 8;
                uint ad = smem_u32(&sBh[brow][bcol]);
                ldsm4t(bh[np*2][0], bh[np*2][1], bh[np*2+1][0], bh[np*2+1][1], ad);
                ad = smem_u32(&sBl[brow][bcol]);
                ldsm4t(bl[np*2][0], bl[np*2][1], bl[np*2+1][0], bl[np*2+1][1], ad);
            }
            #pragma unroll
            for (int mt = 0; mt < 2; mt++) {
                int arow = mw + mt * 16 + lr + (sel & 1) * 8;
                int acol = kk + (sel >> 1) * 8;
                uint ah[4], al[4];
                uint ad = smem_u32(&sAh[arow][acol]);
                ldsm4(ah[0], ah[1], ah[2], ah[3], ad);
                ad = smem_u32(&sAl[arow][acol]);
                ldsm4(al[0], al[1], al[2], al[3], ad);
                #pragma unroll
                for (int nt = 0; nt < 4; nt++) {
                    mma_bf16(c[mt][nt], ah, bh[nt]);
                    mma_bf16(c[mt][nt], al, bh[nt]);
                    mma_bf16(c[mt][nt], ah, bl[nt]);
                }
            }
        }
        __syncthreads();
    }

    // epilogue: bias + leaky. Fragment: c0,c1 -> row g, cols 2q,2q+1; c2,c3 -> row g+8.
    int g  = lane >> 2;
    int q4 = lane & 3;
    #pragma unroll
    for (int mt = 0; mt < 2; mt++) {
        #pragma unroll
        for (int half = 0; half < 2; half++) {
            int gr = m0 + mw + mt * 16 + g + half * 8;
            if (gr < NI) {
                float* crow = C + (size_t)gr * 64;
                #pragma unroll
                for (int nt = 0; nt < 4; nt++) {
                    int col = nw + nt * 8 + 2 * q4;
                    float b0 = bias[col], b1 = bias[col + 1];
                    float v0 = lrelu(c[mt][nt][half * 2]     + b0);
                    float v1 = lrelu(c[mt][nt][half * 2 + 1] + b1);
                    *(float2*)&crow[col] = make_float2(v0, v1);
                }
            }
        }
    }
}

// l2norm item-feature rows of xm[mod] in place (NI rows), mod = blockIdx.y.
__global__ void k_l2norm_feat() {
    int mod = blockIdx.y;
    int row = blockIdx.x * 8 + (threadIdx.x >> 5);
    if (row >= NI) return;
    float* f = g_xm + (size_t)mod * NN * D + (size_t)(NU + row) * D;
    int lane = threadIdx.x & 31;
    float a = f[lane];
    float b = f[32 + lane];
    float ss = a * a + b * b;
    #pragma unroll
    for (int o = 16; o; o >>= 1) ss += __shfl_xor_sync(0xffffffffu, ss, o);
    float inv = rsqrtf(fmaxf(ss, 1e-24f));
    f[lane]      = a * inv;
    f[32 + lane] = b * inv;
}

// pref rows of xm[mod] = l2norm(input), mod = blockIdx.y.
__global__ void k_l2norm_pref(const float* __restrict__ in0, const float* __restrict__ in1) {
    int mod = blockIdx.y;
    const float* in = mod ? in1 : in0;
    int row = blockIdx.x * 8 + (threadIdx.x >> 5);
    if (row >= NU) return;
    float* p = g_xm + (size_t)mod * NN * D + (size_t)row * D;
    int lane = threadIdx.x & 31;
    float a = in[(size_t)row * 64 + lane];
    float b = in[(size_t)row * 64 + 32 + lane];
    float ss = a * a + b * b;
    #pragma unroll
    for (int o = 16; o; o >>= 1) ss += __shfl_xor_sync(0xffffffffu, ss, o);
    float inv = rsqrtf(fmaxf(ss, 1e-24f));
    p[lane]      = a * inv;
    p[32 + lane] = b * inv;
}

// g_hx slot0 = l2norm(id_emb) (NN rows).
__global__ void k_l2norm_x(const float* __restrict__ in) {
    int row = blockIdx.x * 8 + (threadIdx.x >> 5);
    if (row >= NN) return;
    int lane = threadIdx.x & 31;
    float a = in[(size_t)row * 64 + lane];
    float b = in[(size_t)row * 64 + 32 + lane];
    float ss = a * a + b * b;
    #pragma unroll
    for (int o = 16; o; o >>= 1) ss += __shfl_xor_sync(0xffffffffu, ss, o);
    float inv = rsqrtf(fmaxf(ss, 1e-24f));
    g_hx[(size_t)row * 64 + lane]      = a * inv;
    g_hx[(size_t)row * 64 + 32 + lane] = b * inv;
}

// ------------------- GAT (single-pass softmax, chunked MLP=4 gather) -------------------
__global__ void k_gat_node(int nNodes, int mode, float* __restrict__ out) {
    int n = blockIdx.x * 8 + (threadIdx.x >> 5);
    if (n >= nNodes) return;
    int mod = blockIdx.y;
    float* xbase = g_xm + (size_t)mod * NN * D;
    int lane = threadIdx.x & 31;
    int beg = g_offG[n];
    int end = beg + g_degG[n];

    float2 xd = *(const float2*)&xbase[(size_t)n * D + lane * 2];

    float* ebuf = g_e + (size_t)mod * E;
    float s = 0.f, ax = 0.f, ay = 0.f;
    for (int p0 = beg; p0 < end; p0 += 4) {
        int cnt = end - p0;
        if (cnt > 4) cnt = 4;
        float2 vv[4];
        int sidx[4];
        #pragma unroll
        for (int j = 0; j < 4; j++)
            if (j < cnt) sidx[j] = g_csrG_src[p0 + j];
        #pragma unroll
        for (int j = 0; j < 4; j++)
            if (j < cnt) vv[j] = *(const float2*)&xbase[(size_t)sidx[j] * D + lane * 2];
        #pragma unroll
        for (int j = 0; j < 4; j++) {
            if (j < cnt) {
                float dt = xd.x * vv[j].x + xd.y * vv[j].y;
                #pragma unroll
                for (int o = 16; o; o >>= 1) dt += __shfl_xor_sync(0xffffffffu, dt, o);
                float ex = __expf(dt);
                if (mode == 1 && lane == 0) ebuf[p0 + j] = ex;
                s  += ex;
                ax += ex * vv[j].x;
                ay += ex * vv[j].y;
            }
        }
    }

    if (mode == 0) {
        float invs = 1.f / (s + 1e-16f);
        float nx = xd.x + ax * invs;
        float ny = xd.y + ay * invs;
        float ss = nx * nx + ny * ny;
        #pragma unroll
        for (int o = 16; o; o >>= 1) ss += __shfl_xor_sync(0xffffffffu, ss, o);
        float inv = rsqrtf(fmaxf(ss, 1e-24f));
        xbase[(size_t)n * D + lane * 2]     = nx * inv;
        xbase[(size_t)n * D + lane * 2 + 1] = ny * inv;
    } else {
        float inv2 = 1.f / (2.f * s + 1e-16f);
        float* alpha = g_alpha + (size_t)mod * E;
        __syncwarp();
        for (int p = beg + lane; p < end; p += 32)
            alpha[p] = ebuf[p] * inv2;
        float sc = inv2 + inv2;
        int c = lane * 2;
        out[(size_t)n * OD + 64 + mod * 64 + c]     = xd.x + lrelu(ax * sc);
        out[(size_t)n * OD + 64 + mod * 64 + c + 1] = xd.y + lrelu(ay * sc);
    }
}

// SAGE gather (chunked). layer 1 computes g_wc inline; layer 2 reads g_wc.
__global__ void k_sage_node(int layer, const float* __restrict__ conf, float* __restrict__ out) {
    int n = blockIdx.x * 8 + (threadIdx.x >> 5);
    if (n >= NN) return;
    const float* xin = g_hx + (size_t)(layer - 1) * NN * D;
    int lane = threadIdx.x & 31;
    int beg = g_offG[n];
    int cnt0 = g_degG[n];
    int end = beg + cnt0;
    float ax = 0.f, ay = 0.f;

    for (int p0 = beg; p0 < end; p0 += 4) {
        int cnt = end - p0;
        if (cnt > 4) cnt = 4;
        int sidx[4];
        float w[4];
        #pragma unroll
        for (int j = 0; j < 4; j++)
            if (j < cnt) sidx[j] = g_csrG_src[p0 + j];
        if (layer == 1) {
            #pragma unroll
            for (int j = 0; j < 4; j++)
                if (j < cnt) {
                    float wv = g_alpha[p0 + j];
                    float wt = g_alpha[E + p0 + j];
                    float2 cf = *(const float2*)&conf[2 * sidx[j]];
                    w[j] = fmaxf(fmaxf(wv * cf.x, wt * cf.y), 0.f);
                    if (lane == 0) g_wc[p0 + j] = w[j];
                }
        } else {
            #pragma unroll
            for (int j = 0; j < 4; j++)
                if (j < cnt) w[j] = g_wc[p0 + j];
        }
        float2 vv[4];
        #pragma unroll
        for (int j = 0; j < 4; j++)
            if (j < cnt && w[j] != 0.f)
                vv[j] = *(const float2*)&xin[(size_t)sidx[j] * D + lane * 2];
        #pragma unroll
        for (int j = 0; j < 4; j++)
            if (j < cnt && w[j] != 0.f) {
                ax += w[j] * vv[j].x;
                ay += w[j] * vv[j].y;
            }
    }

    float invd = 1.f / fmaxf((float)cnt0, 1.f);
    float hx = lrelu(ax * invd), hy = lrelu(ay * invd);
    int c = lane * 2;
    if (layer == 1) {
        g_hx[(size_t)NN * D + (size_t)n * D + c]     = hx;
        g_hx[(size_t)NN * D + (size_t)n * D + c + 1] = hy;
    } else {
        size_t b = (size_t)n * D + c;
        out[(size_t)n * OD + c]     = g_hx[b]     + g_hx[(size_t)NN * D + b]     + hx;
        out[(size_t)n * OD + c + 1] = g_hx[b + 1] + g_hx[(size_t)NN * D + b + 1] + hy;
    }
}

// ------------------- launch -------------------
extern "C" void kernel_launch(void* const* d_in, const int* in_sizes, int n_in,
                              void* d_out, int out_size) {
    const void* ei = nullptr;
    const float *v_feat = 0, *t_feat = 0, *pref_v = 0, *pref_t = 0;
    const float *W_v = 0, *b_v = 0, *W_t = 0, *b_t = 0, *id_emb = 0, *conf = 0;
    for (int i = 0; i < n_in; i++) {
        long long sz = in_sizes[i];
        const void* p = d_in[i];
        switch (sz) {
            case 2000000LL:  ei = p; break;
            case 81920000LL: v_feat = (const float*)p; break;
            case 15360000LL: t_feat = (const float*)p; break;
            case 3200000LL:  if (!pref_v) pref_v = (const float*)p; else pref_t = (const float*)p; break;
            case 131072LL:   W_v = (const float*)p; break;
            case 24576LL:    W_t = (const float*)p; break;
            case 64LL:       if (!b_v) b_v = (const float*)p; else b_t = (const float*)p; break;
            case 5760000LL:  id_emb = (const float*)p; break;
            case 180000LL:   conf = (const float*)p; break;
            default: break;
        }
    }
    float* out = (float*)d_out;

    const int B = 256;
    const int nScanB = divup(NN, 1024);
    dim3 gU(divup(NU, 8), 2);
    dim3 gA(divup(NN, 8), 2);
    dim3 gF(divup(NI, 8), 2);

    // graph construction
    k_sniff<<<1, 32>>>((const int*)ei);
    k_zero <<<divup(NN, B), B>>>();
    k_build<<<divup(E, B), B>>>(ei);
    k_scan1<<<nScanB, 1024>>>();
    k_scan2<<<1, 128>>>(nScanB);
    k_scan3<<<nScanB, 1024>>>();
    k_place<<<divup(E, B), B>>>();

    // both content branches, batched (tensor-core GEMM)
    k_gemm_both<<<2 * GB, 256>>>(v_feat, W_v, b_v, t_feat, W_t, b_t);
    k_l2norm_feat<<<gF, 256>>>();
    k_l2norm_pref<<<gU, 256>>>(pref_v, pref_t);
    k_l2norm_x<<<divup(NN, 8), 256>>>(id_emb);

    for (int it = 0; it < 3; it++)
        k_gat_node<<<gU, 256>>>(NU, 0, nullptr);
    k_gat_node<<<gA, 256>>>(NN, 1, out);

    // SAGE (layer 1 computes edge weights inline)
    k_sage_node<<<divup(NN, 8), 256>>>(1, conf, nullptr);
    k_sage_node<<<divup(NN, 8), 256>>>(2, conf, out);
}